// round 1
// baseline (speedup 1.0000x reference)
#include <cuda_runtime.h>
#include <math.h>

#define C 128
#define MAX_M (1 << 17)   // 131072 >= M (100000)

// Scratch: per-bag loss (allocation-free per harness rules)
__device__ float g_bag_loss[MAX_M];

// One CTA per bag, one thread per class.
__global__ void mil_ce_bag_kernel(const float* __restrict__ input,
                                  const int*   __restrict__ target,
                                  const int*   __restrict__ bag,
                                  float*       __restrict__ loss,
                                  int N, int M)
{
    const int b = blockIdx.x;
    if (b >= M) return;
    const int t = threadIdx.x;

    __shared__ int s_range[2];
    // Two threads binary-search the bag's [start, end) in the sorted bag array.
    if (t < 2) {
        int key = b + t;              // t==0 -> lower_bound(b), t==1 -> lower_bound(b+1)
        int lo = 0, hi = N;
        while (lo < hi) {
            int mid = (lo + hi) >> 1;
            if (bag[mid] < key) lo = mid + 1; else hi = mid;
        }
        s_range[t] = lo;
    }
    __syncthreads();
    const int start = s_range[0];
    const int n     = s_range[1] - start;

    // Per-class max over the bag's rows. Coalesced: thread t reads column t.
    const float* p = input + (size_t)start * C + t;
    float m0 = -INFINITY, m1 = -INFINITY, m2 = -INFINITY, m3 = -INFINITY;
    int r = 0;
    for (; r + 4 <= n; r += 4) {
        float v0 = p[(size_t)(r + 0) * C];
        float v1 = p[(size_t)(r + 1) * C];
        float v2 = p[(size_t)(r + 2) * C];
        float v3 = p[(size_t)(r + 3) * C];
        m0 = fmaxf(m0, v0);
        m1 = fmaxf(m1, v1);
        m2 = fmaxf(m2, v2);
        m3 = fmaxf(m3, v3);
    }
    for (; r < n; ++r) m0 = fmaxf(m0, p[(size_t)r * C]);
    const float m = fmaxf(fmaxf(m0, m1), fmaxf(m2, m3));

    // Block logsumexp over the 128 per-class maxima.
    __shared__ float sval[C];   // keep raw maxima (need sval[target[b]])
    __shared__ float sred[C];   // reduction buffer
    sval[t] = m;
    sred[t] = m;
    __syncthreads();
    #pragma unroll
    for (int off = C / 2; off >= 1; off >>= 1) {
        if (t < off) sred[t] = fmaxf(sred[t], sred[t + off]);
        __syncthreads();
    }
    const float bmax = sred[0];
    __syncthreads();
    sred[t] = expf(m - bmax);
    __syncthreads();
    #pragma unroll
    for (int off = C / 2; off >= 1; off >>= 1) {
        if (t < off) sred[t] += sred[t + off];
        __syncthreads();
    }
    if (t == 0) {
        const float picked = sval[target[b]];
        loss[b] = bmax + logf(sred[0]) - picked;
    }
}

// Deterministic mean over M per-bag losses (single block, no atomics).
__global__ void mil_ce_reduce_kernel(const float* __restrict__ loss,
                                     float* __restrict__ out, int M)
{
    __shared__ float s[1024];
    float acc = 0.0f;
    for (int i = threadIdx.x; i < M; i += 1024) acc += loss[i];
    s[threadIdx.x] = acc;
    __syncthreads();
    #pragma unroll
    for (int off = 512; off >= 1; off >>= 1) {
        if (threadIdx.x < off) s[threadIdx.x] += s[threadIdx.x + off];
        __syncthreads();
    }
    if (threadIdx.x == 0) out[0] = s[0] / (float)M;
}

extern "C" void kernel_launch(void* const* d_in, const int* in_sizes, int n_in,
                              void* d_out, int out_size)
{
    const float* input  = (const float*)d_in[0];   // [N, C] f32
    const int*   target = (const int*)  d_in[1];   // [M] i32
    const int*   bag    = (const int*)  d_in[2];   // [N] i32 (sorted, contiguous)
    float*       out    = (float*)d_out;

    const int M = in_sizes[1];
    const int N = in_sizes[2];

    float* loss;
    cudaGetSymbolAddress((void**)&loss, g_bag_loss);

    mil_ce_bag_kernel<<<M, C>>>(input, target, bag, loss, N, M);
    mil_ce_reduce_kernel<<<1, 1024>>>(loss, out, M);
}

// round 2
// speedup vs baseline: 1.5697x; 1.5697x over previous
#include <cuda_runtime.h>
#include <math.h>

#define C 128
#define MAX_M (1 << 17)   // 131072 >= M (100000)

// Allocation-free scratch (per harness rules)
__device__ float g_bag_loss[MAX_M];
__device__ int   g_start[MAX_M + 1];
__device__ float g_partial[256];

static __device__ __forceinline__ float4 max4(float4 a, float4 b) {
    float4 r;
    r.x = fmaxf(a.x, b.x); r.y = fmaxf(a.y, b.y);
    r.z = fmaxf(a.z, b.z); r.w = fmaxf(a.w, b.w);
    return r;
}

// Pass 1: streaming boundary detection over the sorted bag array.
// g_start[k] = first row index of bag k; g_start[M] = N. Handles empty bags.
__global__ void mil_boundaries_kernel(const int* __restrict__ bag, int N, int M)
{
    int i = blockIdx.x * blockDim.x + threadIdx.x;
    if (i >= N) return;
    int b = bag[i];
    int prev = (i == 0) ? -1 : bag[i - 1];
    if (b != prev) {
        for (int k = prev + 1; k <= b; ++k) g_start[k] = i;
    }
    if (i == N - 1) {
        for (int k = b + 1; k <= M; ++k) g_start[k] = N;
    }
}

// Pass 2: one CTA per bag. 128 threads = 4 row-groups x 32 lanes.
// Lane l owns classes [4l, 4l+4) via float4 loads (LDG.128, fully coalesced).
__global__ void __launch_bounds__(128)
mil_ce_bag_kernel(const float4* __restrict__ input,   // [N, 32] float4 view of [N, C]
                  const int*    __restrict__ target,
                  float*        __restrict__ loss,
                  int M)
{
    const int b = blockIdx.x;
    if (b >= M) return;
    const int t    = threadIdx.x;
    const int lane = t & 31;
    const int grp  = t >> 5;

    const int start = g_start[b];
    const int n     = g_start[b + 1] - start;

    const float4* p = input + (size_t)start * 32 + lane;  // row stride = 32 float4

    float4 m0 = make_float4(-INFINITY, -INFINITY, -INFINITY, -INFINITY);
    float4 m1 = m0;

    // Row-groups stride by 4; 2-way unroll -> 2 independent LDG.128 in flight.
    int r = grp;
    for (; r + 4 < n; r += 8) {
        float4 a = __ldg(p + (size_t)r * 32);
        float4 c = __ldg(p + (size_t)(r + 4) * 32);
        m0 = max4(m0, a);
        m1 = max4(m1, c);
    }
    for (; r < n; r += 4) m0 = max4(m0, __ldg(p + (size_t)r * 32));
    m0 = max4(m0, m1);

    // Combine the 4 row-groups per lane through shared memory.
    __shared__ float4 sgrp[4][32];
    __shared__ float  sval[C];
    sgrp[grp][lane] = m0;
    __syncthreads();

    if (t < 32) {
        float4 a  = sgrp[0][t];
        float4 b2 = sgrp[1][t];
        float4 c  = sgrp[2][t];
        float4 d  = sgrp[3][t];
        float4 mm = max4(max4(a, b2), max4(c, d));

        // Expose per-class maxima for the target lookup.
        sval[4 * t + 0] = mm.x;
        sval[4 * t + 1] = mm.y;
        sval[4 * t + 2] = mm.z;
        sval[4 * t + 3] = mm.w;

        // Warp logsumexp over 128 classes (4 per lane).
        float tm = fmaxf(fmaxf(mm.x, mm.y), fmaxf(mm.z, mm.w));
        #pragma unroll
        for (int off = 16; off >= 1; off >>= 1)
            tm = fmaxf(tm, __shfl_xor_sync(0xffffffffu, tm, off));

        float s = expf(mm.x - tm) + expf(mm.y - tm)
                + expf(mm.z - tm) + expf(mm.w - tm);
        #pragma unroll
        for (int off = 16; off >= 1; off >>= 1)
            s += __shfl_xor_sync(0xffffffffu, s, off);

        __syncwarp();  // make sval[] writes visible to lane 0
        if (t == 0) {
            const float picked = sval[target[b]];
            loss[b] = tm + logf(s) - picked;
        }
    }
}

// Deterministic two-stage mean.
__global__ void mil_reduce1_kernel(const float* __restrict__ loss, int M)
{
    __shared__ float s[256];
    float acc = 0.0f;
    for (int i = blockIdx.x * 256 + threadIdx.x; i < M; i += 256 * 256)
        acc += loss[i];
    s[threadIdx.x] = acc;
    __syncthreads();
    #pragma unroll
    for (int off = 128; off >= 1; off >>= 1) {
        if (threadIdx.x < off) s[threadIdx.x] += s[threadIdx.x + off];
        __syncthreads();
    }
    if (threadIdx.x == 0) g_partial[blockIdx.x] = s[0];
}

__global__ void mil_reduce2_kernel(float* __restrict__ out, int M)
{
    __shared__ float s[256];
    s[threadIdx.x] = g_partial[threadIdx.x];
    __syncthreads();
    #pragma unroll
    for (int off = 128; off >= 1; off >>= 1) {
        if (threadIdx.x < off) s[threadIdx.x] += s[threadIdx.x + off];
        __syncthreads();
    }
    if (threadIdx.x == 0) out[0] = s[0] / (float)M;
}

extern "C" void kernel_launch(void* const* d_in, const int* in_sizes, int n_in,
                              void* d_out, int out_size)
{
    const float* input  = (const float*)d_in[0];   // [N, C] f32
    const int*   target = (const int*)  d_in[1];   // [M] i32
    const int*   bag    = (const int*)  d_in[2];   // [N] i32 (sorted, contiguous)
    float*       out    = (float*)d_out;

    const int M = in_sizes[1];
    const int N = in_sizes[2];

    float* loss;
    cudaGetSymbolAddress((void**)&loss, g_bag_loss);

    mil_boundaries_kernel<<<(N + 255) / 256, 256>>>(bag, N, M);
    mil_ce_bag_kernel<<<M, 128>>>((const float4*)input, target, loss, M);
    mil_reduce1_kernel<<<256, 256>>>(loss, M);
    mil_reduce2_kernel<<<1, 256>>>(out, M);
}

// round 3
// speedup vs baseline: 1.6434x; 1.0469x over previous
#include <cuda_runtime.h>
#include <math.h>

#define C 128
#define MAX_M (1 << 17)   // 131072 >= M (100000)
#define BAGS_PER_CTA 8

// Allocation-free scratch (per harness rules)
__device__ float g_bag_loss[MAX_M];
__device__ int   g_start[MAX_M + 1];
__device__ unsigned int g_done;   // last-block election counter (reset each replay)

static __device__ __forceinline__ float4 max4(float4 a, float4 b) {
    float4 r;
    r.x = fmaxf(a.x, b.x); r.y = fmaxf(a.y, b.y);
    r.z = fmaxf(a.z, b.z); r.w = fmaxf(a.w, b.w);
    return r;
}

// Pass 1: streaming boundary detection over the sorted bag array.
// Also resets the last-block counter for graph replay.
__global__ void mil_boundaries_kernel(const int* __restrict__ bag, int N, int M)
{
    int i = blockIdx.x * blockDim.x + threadIdx.x;
    if (i == 0) g_done = 0u;
    if (i >= N) return;
    int b = bag[i];
    int prev = (i == 0) ? -1 : bag[i - 1];
    if (b != prev) {
        for (int k = prev + 1; k <= b; ++k) g_start[k] = i;
    }
    if (i == N - 1) {
        for (int k = b + 1; k <= M; ++k) g_start[k] = N;
    }
}

// Pass 2: one WARP per bag. Lane l owns classes [4l, 4l+4) via float4 loads;
// a warp covers one full 512B row per iteration. No shared memory, no
// __syncthreads in the hot path. Last CTA performs the deterministic mean.
__global__ void __launch_bounds__(256)
mil_ce_bag_kernel(const float4* __restrict__ input,   // [N, 32] float4 view of [N, C]
                  const int*    __restrict__ target,
                  float*        __restrict__ loss,
                  float*        __restrict__ out,
                  int M, int nblocks)
{
    const int lane = threadIdx.x & 31;
    const int wid  = threadIdx.x >> 5;
    const int b    = blockIdx.x * BAGS_PER_CTA + wid;

    if (b < M) {
        const int start = g_start[b];
        const int n     = g_start[b + 1] - start;

        const float4* p = input + (size_t)start * 32 + lane;  // row stride = 32 float4

        float4 m0 = make_float4(-INFINITY, -INFINITY, -INFINITY, -INFINITY);
        float4 m1 = m0, m2 = m0, m3 = m0;

        int r = 0;
        for (; r + 4 <= n; r += 4) {        // 4 independent LDG.128 in flight
            float4 a = __ldg(p + (size_t)(r + 0) * 32);
            float4 c = __ldg(p + (size_t)(r + 1) * 32);
            float4 d = __ldg(p + (size_t)(r + 2) * 32);
            float4 e = __ldg(p + (size_t)(r + 3) * 32);
            m0 = max4(m0, a);
            m1 = max4(m1, c);
            m2 = max4(m2, d);
            m3 = max4(m3, e);
        }
        for (; r < n; ++r) m0 = max4(m0, __ldg(p + (size_t)r * 32));
        float4 mm = max4(max4(m0, m1), max4(m2, m3));

        // Warp logsumexp over 128 classes (4 per lane).
        float tm = fmaxf(fmaxf(mm.x, mm.y), fmaxf(mm.z, mm.w));
        #pragma unroll
        for (int off = 16; off >= 1; off >>= 1)
            tm = fmaxf(tm, __shfl_xor_sync(0xffffffffu, tm, off));

        float s = expf(mm.x - tm) + expf(mm.y - tm)
                + expf(mm.z - tm) + expf(mm.w - tm);
        #pragma unroll
        for (int off = 16; off >= 1; off >>= 1)
            s += __shfl_xor_sync(0xffffffffu, s, off);

        // picked = per-class max of the target class (lane tc>>2, component tc&3)
        int tc = 0;
        if (lane == 0) tc = target[b];
        tc = __shfl_sync(0xffffffffu, tc, 0);
        const int comp = tc & 3;
        float v = (comp == 0) ? mm.x : (comp == 1) ? mm.y : (comp == 2) ? mm.z : mm.w;
        const float picked = __shfl_sync(0xffffffffu, v, tc >> 2);

        if (lane == 0) loss[b] = tm + logf(s) - picked;
    }

    // ---- last-CTA deterministic mean ----
    __syncthreads();
    __shared__ unsigned int s_rank;
    if (threadIdx.x == 0) {
        __threadfence();                       // publish loss[] writes
        s_rank = atomicAdd(&g_done, 1u);
    }
    __syncthreads();
    if (s_rank == (unsigned int)(nblocks - 1)) {
        __threadfence();                       // acquire other CTAs' loss[] writes
        __shared__ float sred[256];
        float acc = 0.0f;
        for (int i = threadIdx.x; i < M; i += 256) acc += loss[i];   // fixed order
        sred[threadIdx.x] = acc;
        __syncthreads();
        #pragma unroll
        for (int off = 128; off >= 1; off >>= 1) {
            if (threadIdx.x < off) sred[threadIdx.x] += sred[threadIdx.x + off];
            __syncthreads();
        }
        if (threadIdx.x == 0) out[0] = sred[0] / (float)M;
    }
}

extern "C" void kernel_launch(void* const* d_in, const int* in_sizes, int n_in,
                              void* d_out, int out_size)
{
    const float* input  = (const float*)d_in[0];   // [N, C] f32
    const int*   target = (const int*)  d_in[1];   // [M] i32
    const int*   bag    = (const int*)  d_in[2];   // [N] i32 (sorted, contiguous)
    float*       out    = (float*)d_out;

    const int M = in_sizes[1];
    const int N = in_sizes[2];

    float* loss;
    cudaGetSymbolAddress((void**)&loss, g_bag_loss);

    const int nblocks = (M + BAGS_PER_CTA - 1) / BAGS_PER_CTA;

    mil_boundaries_kernel<<<(N + 255) / 256, 256>>>(bag, N, M);
    mil_ce_bag_kernel<<<nblocks, 256>>>((const float4*)input, target, loss, out,
                                        M, nblocks);
}

// round 4
// speedup vs baseline: 1.7150x; 1.0436x over previous
#include <cuda_runtime.h>
#include <math.h>

#define C 128
#define MAX_M (1 << 17)   // 131072 >= M (100000)
#define BAGS_PER_CTA 8

// Allocation-free scratch (per harness rules)
__device__ float g_bag_loss[MAX_M];
__device__ int   g_start[MAX_M + 1];
__device__ unsigned int g_done;   // last-block election counter (reset each replay)

static __device__ __forceinline__ float4 max4(float4 a, float4 b) {
    float4 r;
    r.x = fmaxf(a.x, b.x); r.y = fmaxf(a.y, b.y);
    r.z = fmaxf(a.z, b.z); r.w = fmaxf(a.w, b.w);
    return r;
}

// Pass 1: streaming boundary detection over the sorted bag array.
// Also resets the last-block counter for graph replay.
__global__ void mil_boundaries_kernel(const int* __restrict__ bag, int N, int M)
{
    int i = blockIdx.x * blockDim.x + threadIdx.x;
    if (i == 0) g_done = 0u;
    if (i >= N) return;
    int b = bag[i];
    int prev = (i == 0) ? -1 : bag[i - 1];
    if (b != prev) {
        for (int k = prev + 1; k <= b; ++k) g_start[k] = i;
    }
    if (i == N - 1) {
        for (int k = b + 1; k <= M; ++k) g_start[k] = N;
    }
}

// Pass 2: one WARP per bag, 8 bags per CTA. Lane l owns classes [4l, 4l+4).
// g_start fetched once per CTA (coalesced) into shared. Streaming loads use
// evict-first policy (read-once 1GB stream). Last CTA does the deterministic mean.
__global__ void __launch_bounds__(256, 6)
mil_ce_bag_kernel(const float4* __restrict__ input,   // [N, 32] float4 view of [N, C]
                  const int*    __restrict__ target,
                  float*        __restrict__ loss,
                  float*        __restrict__ out,
                  int M, int nblocks)
{
    const int lane = threadIdx.x & 31;
    const int wid  = threadIdx.x >> 5;
    const int b0   = blockIdx.x * BAGS_PER_CTA;
    const int b    = b0 + wid;

    // CTA-cooperative boundary fetch: one transaction instead of 16 serial loads.
    __shared__ int s_start[BAGS_PER_CTA + 1];
    {
        int k = b0 + threadIdx.x;
        if (threadIdx.x <= BAGS_PER_CTA && k <= M)
            s_start[threadIdx.x] = g_start[k];
    }
    __syncthreads();

    if (b < M) {
        const int start = s_start[wid];
        const int n     = s_start[wid + 1] - start;

        const float4* p = input + (size_t)start * 32 + lane;  // row stride = 32 float4

        float4 m0 = make_float4(-INFINITY, -INFINITY, -INFINITY, -INFINITY);
        float4 m1 = m0, m2 = m0, m3 = m0;

        int r = 0;
        for (; r + 4 <= n; r += 4) {        // 4 independent LDG.128 in flight
            float4 a = __ldcs(p + (size_t)(r + 0) * 32);
            float4 c = __ldcs(p + (size_t)(r + 1) * 32);
            float4 d = __ldcs(p + (size_t)(r + 2) * 32);
            float4 e = __ldcs(p + (size_t)(r + 3) * 32);
            m0 = max4(m0, a);
            m1 = max4(m1, c);
            m2 = max4(m2, d);
            m3 = max4(m3, e);
        }
        for (; r < n; ++r) m0 = max4(m0, __ldcs(p + (size_t)r * 32));
        float4 mm = max4(max4(m0, m1), max4(m2, m3));

        // Warp logsumexp over 128 classes (4 per lane).
        float tm = fmaxf(fmaxf(mm.x, mm.y), fmaxf(mm.z, mm.w));
        #pragma unroll
        for (int off = 16; off >= 1; off >>= 1)
            tm = fmaxf(tm, __shfl_xor_sync(0xffffffffu, tm, off));

        float s = expf(mm.x - tm) + expf(mm.y - tm)
                + expf(mm.z - tm) + expf(mm.w - tm);
        #pragma unroll
        for (int off = 16; off >= 1; off >>= 1)
            s += __shfl_xor_sync(0xffffffffu, s, off);

        // picked = per-class max of the target class (lane tc>>2, component tc&3)
        int tc = 0;
        if (lane == 0) tc = target[b];
        tc = __shfl_sync(0xffffffffu, tc, 0);
        const int comp = tc & 3;
        float v = (comp == 0) ? mm.x : (comp == 1) ? mm.y : (comp == 2) ? mm.z : mm.w;
        const float picked = __shfl_sync(0xffffffffu, v, tc >> 2);

        if (lane == 0) loss[b] = tm + logf(s) - picked;
    }

    // ---- last-CTA deterministic mean ----
    __syncthreads();
    __shared__ unsigned int s_rank;
    if (threadIdx.x == 0) {
        __threadfence();                       // publish loss[] writes
        s_rank = atomicAdd(&g_done, 1u);
    }
    __syncthreads();
    if (s_rank == (unsigned int)(nblocks - 1)) {
        __threadfence();                       // acquire other CTAs' loss[] writes
        __shared__ float sred[256];
        float acc = 0.0f;
        for (int i = threadIdx.x; i < M; i += 256) acc += loss[i];   // fixed order
        sred[threadIdx.x] = acc;
        __syncthreads();
        #pragma unroll
        for (int off = 128; off >= 1; off >>= 1) {
            if (threadIdx.x < off) sred[threadIdx.x] += sred[threadIdx.x + off];
            __syncthreads();
        }
        if (threadIdx.x == 0) out[0] = sred[0] / (float)M;
    }
}

extern "C" void kernel_launch(void* const* d_in, const int* in_sizes, int n_in,
                              void* d_out, int out_size)
{
    const float* input  = (const float*)d_in[0];   // [N, C] f32
    const int*   target = (const int*)  d_in[1];   // [M] i32
    const int*   bag    = (const int*)  d_in[2];   // [N] i32 (sorted, contiguous)
    float*       out    = (float*)d_out;

    const int M = in_sizes[1];
    const int N = in_sizes[2];

    float* loss;
    cudaGetSymbolAddress((void**)&loss, g_bag_loss);

    const int nblocks = (M + BAGS_PER_CTA - 1) / BAGS_PER_CTA;

    mil_boundaries_kernel<<<(N + 255) / 256, 256>>>(bag, N, M);
    mil_ce_bag_kernel<<<nblocks, 256>>>((const float4*)input, target, loss, out,
                                        M, nblocks);
}